// round 10
// baseline (speedup 1.0000x reference)
#include <cuda_runtime.h>
#include <math.h>

// CharRNN fused persistent kernel, round 10.
// B=512, L=1024, E=32, H=128, V=32.
// Phase 1 (sequential): 256 CTAs x 128 threads, 2 rows/CTA, 2 CTAs/SM.
//   Thread j holds the full W_hh column j in 64 f32x2 regs. Per step: one
//   __syncthreads, recurrence ONLY; h(t) streamed to global scratch.
// Phase 2 (bulk, same CTA): logits = Hscratch @ W_hy as a dependency-free
//   GEMM; W_hy pairs loaded into the SAME register array (W_hh is dead).

#define ULL unsigned long long

__device__ float hsc[67108864];   // [512 rows][1024 t][128 j] h history

__device__ __forceinline__ ULL ffma2(ULL a, ULL b, ULL c) {
    ULL d;
    asm("fma.rn.f32x2 %0, %1, %2, %3;" : "=l"(d) : "l"(a), "l"(b), "l"(c));
    return d;
}
__device__ __forceinline__ ULL pack2(float lo, float hi) {
    ULL d;
    asm("mov.b64 %0, {%1, %2};" : "=l"(d) : "f"(lo), "f"(hi));
    return d;
}
__device__ __forceinline__ float sum2(ULL a) {
    float lo, hi;
    asm("mov.b64 {%0, %1}, %2;" : "=f"(lo), "=f"(hi) : "l"(a));
    return lo + hi;
}
// Stable fast tanh: 1 - 2/(exp(2x)+1).
__device__ __forceinline__ float fast_tanh(float x) {
    return 1.0f - __fdividef(2.0f, __expf(2.0f * x) + 1.0f);
}

__global__ void __launch_bounds__(128, 2) charrnn_kernel(
    const int*   __restrict__ x,      // [512][1024]
    const float* __restrict__ emb,    // [32][32]
    const float* __restrict__ Wxh,    // [32][128]
    const float* __restrict__ Whh,    // [128][128]
    const float* __restrict__ bh,     // [128]
    const float* __restrict__ Why,    // [128][32]
    const float* __restrict__ by_g,   // [32]
    float*       __restrict__ out)    // logits [512][1024][32] ++ hidden [512][128]
{
    __shared__ __align__(16) float table[32 * 128];   // xh lookup: [token][j]
    __shared__ __align__(16) float hbuf[2][2 * 128];  // hidden, ping-pong
    __shared__ int xs[2 * 128];                       // token chunk [row][tloc]

    const int tid = threadIdx.x;      // 0..127
    const int j   = tid;
    const int r0  = blockIdx.x * 2;

    // ---- one-time init ----
    for (int c = 0; c < 32; c++) {
        float s = bh[j];
        #pragma unroll 8
        for (int e = 0; e < 32; e++)
            s = fmaf(emb[c * 32 + e], Wxh[e * 128 + j], s);
        table[c * 128 + j] = s;
    }
    hbuf[1][j] = 0.f; hbuf[1][128 + j] = 0.f;   // h_{-1} = 0 (parity 1)

    // W_hh column j, i-pair packed (reused for W_hy in phase 2)
    ULL Wb[64];
    #pragma unroll
    for (int k = 0; k < 64; k++)
        Wb[k] = pack2(Whh[(2 * k) * 128 + j], Whh[(2 * k + 1) * 128 + j]);

    float* scr0 = hsc + (size_t)r0 * 131072;        // row r0 history
    float* scr1 = hsc + (size_t)(r0 + 1) * 131072;  // row r0+1 history

    // ================= Phase 1: recurrence only =================
    for (int t = 0; t < 1024; t++) {
        __syncthreads();                  // h(t-1) visible
        const int tloc = t & 127;
        if (tloc == 0) {
            xs[tid]       = x[r0 * 1024 + t + tid];
            xs[128 + tid] = x[(r0 + 1) * 1024 + t + tid];
            __syncthreads();
        }
        const int br = (t + 1) & 1;       // parity of h(t-1)
        const int bw = t & 1;             // parity of h(t)

        const float* hb = hbuf[br];
        const ulonglong2* h0 = (const ulonglong2*)(hb);
        const ulonglong2* h1 = (const ulonglong2*)(hb + 128);
        const int c0 = xs[tloc];
        const int c1 = xs[128 + tloc];
        ULL a0 = pack2(table[c0 * 128 + j], 0.0f), a1 = 0ull;
        ULL b0 = pack2(table[c1 * 128 + j], 0.0f), b1 = 0ull;
        #pragma unroll
        for (int k = 0; k < 32; k++) {
            ulonglong2 ha = h0[k];
            ulonglong2 hc = h1[k];
            a0 = ffma2(ha.x, Wb[2 * k],     a0);
            b0 = ffma2(hc.x, Wb[2 * k],     b0);
            a1 = ffma2(ha.y, Wb[2 * k + 1], a1);
            b1 = ffma2(hc.y, Wb[2 * k + 1], b1);
        }
        float na = fast_tanh(sum2(a0) + sum2(a1));
        float nb = fast_tanh(sum2(b0) + sum2(b1));
        hbuf[bw][j]       = na;
        hbuf[bw][128 + j] = nb;
        scr0[t * 128 + j] = na;          // fire-and-forget history stream
        scr1[t * 128 + j] = nb;
    }

    // final hidden: h(1023) has parity 1
    out[16777216u + (size_t)r0 * 128 + j]       = hbuf[1][j];
    out[16777216u + (size_t)(r0 + 1) * 128 + j] = hbuf[1][128 + j];

    __threadfence_block();
    __syncthreads();   // all hsc writes by this CTA visible to its threads

    // ================= Phase 2: bulk logits =================
    // Reload Wb with W_hy i-pairs for lane v (W_hh registers are dead).
    const int v = tid & 31;
    const int w = tid >> 5;               // warp 0..3 -> t range [256w, 256w+256)
    #pragma unroll
    for (int k = 0; k < 64; k++)
        Wb[k] = pack2(Why[(2 * k) * 32 + v], Why[(2 * k + 1) * 32 + v]);
    const float byv = by_g[v];

    for (int tt = 0; tt < 256; tt++) {
        const int t = (w << 8) + tt;
        #pragma unroll
        for (int r = 0; r < 2; r++) {
            const ulonglong2* hp =
                (const ulonglong2*)(hsc + (size_t)(r0 + r) * 131072 + t * 128);
            ULL s0 = 0ull, s1 = 0ull, s2 = 0ull, s3 = 0ull;
            #pragma unroll
            for (int k = 0; k < 16; k++) {
                ulonglong2 ha = hp[2 * k];
                ulonglong2 hc = hp[2 * k + 1];
                s0 = ffma2(ha.x, Wb[4 * k],     s0);
                s1 = ffma2(ha.y, Wb[4 * k + 1], s1);
                s2 = ffma2(hc.x, Wb[4 * k + 2], s2);
                s3 = ffma2(hc.y, Wb[4 * k + 3], s3);
            }
            out[((size_t)(r0 + r) * 1024 + t) * 32 + v] =
                sum2(s0) + sum2(s1) + sum2(s2) + sum2(s3) + byv;
        }
    }
}

extern "C" void kernel_launch(void* const* d_in, const int* in_sizes, int n_in,
                              void* d_out, int out_size) {
    (void)in_sizes; (void)n_in; (void)out_size;
    const int*   x   = (const int*)d_in[0];
    const float* emb = (const float*)d_in[1];
    const float* Wxh = (const float*)d_in[2];
    const float* Whh = (const float*)d_in[3];
    const float* bh  = (const float*)d_in[4];
    const float* Why = (const float*)d_in[5];
    const float* by  = (const float*)d_in[6];
    float* out = (float*)d_out;

    charrnn_kernel<<<256, 128>>>(x, emb, Wxh, Whh, bh, Why, by, out);
}